// round 5
// baseline (speedup 1.0000x reference)
#include <cuda_runtime.h>
#include <cuda_bf16.h>
#include <cstdint>

// DiceLoss fused single-kernel, f32x2-packed version (sm_100a).
// predict [16,4,768,768] f32, target [16,768,768] i32, masks [16,768,768] i32 -> f32
//
//   - softmax relative to class 0 (e0 == 1): 3 EX2 + 1 RCP per pixel (MUFU)
//   - all other fp arithmetic packed as f32x2 over pixel pairs (FFMA2 et al.,
//     PTX fma.rn.f32x2 — sm_100+, never auto-generated by ptxas)
//   - den one-hot contributions accumulated as integers on the ALU pipe
//   - threadfence-reduction: last block finalizes, writes out, resets counter

#define NB_PER_N   64
#define N_IMG      16
#define C_CLS      4
#define M_PIX      (768 * 768)
#define M_VEC      (M_PIX / 4)          // 147456 float4 per (n,c)
#define VEC_PER_BLK (M_VEC / NB_PER_N)  // 2304
#define ITERS      (VEC_PER_BLK / 256)  // 9
#define GRID1      (N_IMG * NB_PER_N)   // 1024

typedef unsigned long long u64;

__device__ float g_scratch[GRID1 * 8];
__device__ unsigned int g_count = 0;

__device__ __forceinline__ float ex2f(float x) {
    float y; asm("ex2.approx.f32 %0, %1;" : "=f"(y) : "f"(x)); return y;
}
__device__ __forceinline__ float rcpf(float x) {
    float y; asm("rcp.approx.f32 %0, %1;" : "=f"(y) : "f"(x)); return y;
}

#define PACK2(d, lo, hi)   asm("mov.b64 %0, {%1,%2};" : "=l"(d) : "f"(lo), "f"(hi))
#define UNPACK2(lo, hi, s) asm("mov.b64 {%0,%1}, %2;" : "=f"(lo), "=f"(hi) : "l"(s))
#define MUL2(d, a, b)      asm("mul.rn.f32x2 %0, %1, %2;" : "=l"(d) : "l"(a), "l"(b))
#define ADD2(d, a, b)      asm("add.rn.f32x2 %0, %1, %2;" : "=l"(d) : "l"(a), "l"(b))
#define FMA2(d, a, b, c)   asm("fma.rn.f32x2 %0, %1, %2, %3;" : "=l"(d) : "l"(a), "l"(b), "l"(c))

// Process a pixel pair (a, b). Packed accumulators D0..D3 hold the
// mask-gated squared-softmax den part; sn* hold the num scatter (float);
// sd* hold the integer den one-hot scatter.
__device__ __forceinline__ void px2(
    float x0a, float x0b, float x1a, float x1b,
    float x2a, float x2b, float x3a, float x3b,
    int ta, int tb, int ma, int mb,
    u64 L2E2, u64 mL2E2, u64 ONE2, u64 NEG12,
    u64& D0, u64& D1, u64& D2, u64& D3,
    float& sn0, float& sn1, float& sn2, float& sn3,
    int& sd0, int& sd1, int& sd2, int& sd3)
{
    u64 A, B, C, Dd;
    PACK2(A, x0a, x0b); PACK2(B, x1a, x1b);
    PACK2(C, x2a, x2b); PACK2(Dd, x3a, x3b);

    u64 T0n; MUL2(T0n, A, mL2E2);            // -x0 * log2(e)
    u64 G1;  FMA2(G1, B, L2E2, T0n);
    u64 G2;  FMA2(G2, C, L2E2, T0n);
    u64 G3;  FMA2(G3, Dd, L2E2, T0n);

    float g1a, g1b, g2a, g2b, g3a, g3b;
    UNPACK2(g1a, g1b, G1); UNPACK2(g2a, g2b, G2); UNPACK2(g3a, g3b, G3);
    float e1a = ex2f(g1a), e1b = ex2f(g1b);
    float e2a = ex2f(g2a), e2b = ex2f(g2b);
    float e3a = ex2f(g3a), e3b = ex2f(g3b);

    u64 E1, E2, E3;
    PACK2(E1, e1a, e1b); PACK2(E2, e2a, e2b); PACK2(E3, e3a, e3b);

    u64 S; ADD2(S, E1, E2); ADD2(S, S, E3); ADD2(S, S, ONE2);
    float s_a, s_b; UNPACK2(s_a, s_b, S);
    float r_a = rcpf(s_a), r_b = rcpf(s_b);
    u64 R; PACK2(R, r_a, r_b);

    int ia = (ma != 0) ? 1 : 0;
    int ib = (mb != 0) ? 1 : 0;
    float wfa = (float)ia, wfb = (float)ib;
    u64 W; PACK2(W, wfa, wfb);

    u64 R2;  MUL2(R2, R, R);
    u64 R2W; MUL2(R2W, R2, W);
    ADD2(D0, D0, R2W);
    u64 Q;
    MUL2(Q, E1, E1); FMA2(D1, Q, R2W, D1);
    MUL2(Q, E2, E2); FMA2(D2, Q, R2W, D2);
    MUL2(Q, E3, E3); FMA2(D3, Q, R2W, D3);

    // av = wf * r * e_t + (1 - wf), packed
    float eta = (ta == 0) ? 1.0f : ((ta == 1) ? e1a : ((ta == 2) ? e2a : e3a));
    float etb = (tb == 0) ? 1.0f : ((tb == 1) ? e1b : ((tb == 2) ? e2b : e3b));
    u64 ET; PACK2(ET, eta, etb);
    u64 WR;  MUL2(WR, W, R);
    u64 OMW; FMA2(OMW, W, NEG12, ONE2);
    u64 AV;  FMA2(AV, WR, ET, OMW);
    float ava, avb; UNPACK2(ava, avb, AV);

    int bva = 2 - ia;
    int bvb = 2 - ib;

    if (ta == 0)      { sn0 += ava; sd0 += bva; }
    else if (ta == 1) { sn1 += ava; sd1 += bva; }
    else if (ta == 2) { sn2 += ava; sd2 += bva; }
    else              { sn3 += ava; sd3 += bva; }

    if (tb == 0)      { sn0 += avb; sd0 += bvb; }
    else if (tb == 1) { sn1 += avb; sd1 += bvb; }
    else if (tb == 2) { sn2 += avb; sd2 += bvb; }
    else              { sn3 += avb; sd3 += bvb; }
}

__global__ void __launch_bounds__(256)
dice_fused(const float* __restrict__ pred,
           const int*   __restrict__ tgt,
           const int*   __restrict__ msk,
           float*       __restrict__ out) {
    const int n     = blockIdx.x >> 6;
    const int chunk = blockIdx.x & (NB_PER_N - 1);

    const float4* __restrict__ p0 = (const float4*)(pred + (size_t)(n * 4 + 0) * M_PIX);
    const float4* __restrict__ p1 = (const float4*)(pred + (size_t)(n * 4 + 1) * M_PIX);
    const float4* __restrict__ p2 = (const float4*)(pred + (size_t)(n * 4 + 2) * M_PIX);
    const float4* __restrict__ p3 = (const float4*)(pred + (size_t)(n * 4 + 3) * M_PIX);
    const int4*   __restrict__ tg = (const int4*)(tgt + (size_t)n * M_PIX);
    const int4*   __restrict__ mg = (const int4*)(msk + (size_t)n * M_PIX);

    const int base = chunk * VEC_PER_BLK + threadIdx.x;

    const float L2E = 1.44269504088896340736f;
    u64 L2E2, mL2E2, ONE2, NEG12;
    {
        float l2e = L2E, ml2e = -L2E, one = 1.0f, neg1 = -1.0f;
        PACK2(L2E2, l2e, l2e);
        PACK2(mL2E2, ml2e, ml2e);
        PACK2(ONE2, one, one);
        PACK2(NEG12, neg1, neg1);
    }

    u64 D0, D1, D2, D3;
    {
        float z = 0.0f;
        PACK2(D0, z, z); PACK2(D1, z, z); PACK2(D2, z, z); PACK2(D3, z, z);
    }
    float sn0 = 0.f, sn1 = 0.f, sn2 = 0.f, sn3 = 0.f;
    int   sd0 = 0, sd1 = 0, sd2 = 0, sd3 = 0;

#pragma unroll
    for (int it = 0; it < ITERS; ++it) {
        int i = base + it * 256;
        float4 a = __ldcs(p0 + i);
        float4 b = __ldcs(p1 + i);
        float4 c = __ldcs(p2 + i);
        float4 d = __ldcs(p3 + i);
        int4   t = __ldcs(tg + i);
        int4   m = __ldcs(mg + i);

        px2(a.x, a.y, b.x, b.y, c.x, c.y, d.x, d.y,
            t.x, t.y, m.x, m.y,
            L2E2, mL2E2, ONE2, NEG12,
            D0, D1, D2, D3, sn0, sn1, sn2, sn3, sd0, sd1, sd2, sd3);
        px2(a.z, a.w, b.z, b.w, c.z, c.w, d.z, d.w,
            t.z, t.w, m.z, m.w,
            L2E2, mL2E2, ONE2, NEG12,
            D0, D1, D2, D3, sn0, sn1, sn2, sn3, sd0, sd1, sd2, sd3);
    }

    // merge packed halves + integer den scatter
    float d0lo, d0hi, d1lo, d1hi, d2lo, d2hi, d3lo, d3hi;
    UNPACK2(d0lo, d0hi, D0); UNPACK2(d1lo, d1hi, D1);
    UNPACK2(d2lo, d2hi, D2); UNPACK2(d3lo, d3hi, D3);
    float dv0 = d0lo + d0hi + (float)sd0;
    float dv1 = d1lo + d1hi + (float)sd1;
    float dv2 = d2lo + d2hi + (float)sd2;
    float dv3 = d3lo + d3hi + (float)sd3;

    // ---- deterministic block reduction of 8 accumulators ----
    float v[8] = {sn0, sn1, sn2, sn3, dv0, dv1, dv2, dv3};
#pragma unroll
    for (int k = 0; k < 8; ++k) {
#pragma unroll
        for (int o = 16; o > 0; o >>= 1)
            v[k] += __shfl_xor_sync(0xffffffffu, v[k], o);
    }

    __shared__ float sred[8][8];
    __shared__ bool  s_last;
    int warp = threadIdx.x >> 5;
    int lane = threadIdx.x & 31;
    if (lane == 0) {
#pragma unroll
        for (int k = 0; k < 8; ++k) sred[warp][k] = v[k];
    }
    __syncthreads();

    if (threadIdx.x < 8) {
        float s = 0.f;
#pragma unroll
        for (int w = 0; w < 8; ++w) s += sred[w][threadIdx.x];
        g_scratch[blockIdx.x * 8 + threadIdx.x] = s;
    }

    // ---- completion handshake (release) ----
    __threadfence();
    if (threadIdx.x == 0) {
        unsigned int prev = atomicAdd(&g_count, 1u);
        s_last = (prev == GRID1 - 1);
    }
    __syncthreads();
    if (!s_last) return;

    // ================= last block: finalize (all 256 threads) =============
    __threadfence();   // acquire

    const int tid  = threadIdx.x;
    const int pair = tid >> 2;
    const int q    = tid & 3;
    const int nn   = pair >> 2;
    const int cc   = pair & 3;

    float num = 0.f, den = 0.f;
    const float* sb = g_scratch + ((size_t)(nn * NB_PER_N + q * 16)) * 8;
#pragma unroll
    for (int j = 0; j < 16; ++j) {
        num += __ldcg(sb + j * 8 + cc);
        den += __ldcg(sb + j * 8 + 4 + cc);
    }
    num += __shfl_xor_sync(0xffffffffu, num, 1);
    den += __shfl_xor_sync(0xffffffffu, den, 1);
    num += __shfl_xor_sync(0xffffffffu, num, 2);
    den += __shfl_xor_sync(0xffffffffu, den, 2);

    __shared__ float s_loss[64];
    if (q == 0)
        s_loss[pair] = 1.0f - (num + 1.0f) / (den + 1.0f);   // SMOOTH = 1
    __syncthreads();

    if (tid < 32) {
        float l = s_loss[tid] + s_loss[tid + 32];
#pragma unroll
        for (int o = 16; o > 0; o >>= 1)
            l += __shfl_xor_sync(0xffffffffu, l, o);
        if (tid == 0) {
            out[0] = l * (1.0f / (N_IMG * C_CLS));
            g_count = 0;
        }
    }
}

extern "C" void kernel_launch(void* const* d_in, const int* in_sizes, int n_in,
                              void* d_out, int out_size) {
    const float* pred = (const float*)d_in[0];
    const int*   tgt  = (const int*)d_in[1];
    const int*   msk  = (const int*)d_in[2];
    float*       out  = (float*)d_out;

    dice_fused<<<GRID1, 256>>>(pred, tgt, msk, out);
}